// round 11
// baseline (speedup 1.0000x reference)
#include <cuda_runtime.h>
#include <cstdint>
typedef unsigned long long ull;

#define Bk 32
#define Sk 4096
#define Ik 64
#define Rk 1024
#define Ok 8

#define NB 128
#define THREADS 512
#define JPB 32
// smem byte offsets
#define WT_B   0                 // Wt2[512 kp][33 float2] = 135168
#define RPA_B  135168            // rP engine A: 512 rows x 48B = 24576
#define RPB_B  159744            // rP engine B
#define REDA_B 184320            // red A: 2 x [32][33] floats = 8448
#define REDB_B 192768            // red B
#define SMEM_BYTES 201216

__device__ float g_pre[(size_t)Bk*Sk*Rk];
__device__ float g_rs [(size_t)Bk*Sk*Rk];
__device__ float g_rbufA[2*16*Rk];
__device__ float g_rbufB[2*16*Rk];
__device__ unsigned g_flags[2*NB*32];

__device__ __forceinline__ void fma2(ull& a, ull b, ull c) {
    asm("fma.rn.f32x2 %0, %1, %2, %0;" : "+l"(a) : "l"(b), "l"(c));
}
__device__ __forceinline__ float hsum2(ull a) {
    unsigned l, h; asm("mov.b64 {%0,%1}, %2;" : "=r"(l), "=r"(h) : "l"(a));
    return __uint_as_float(l) + __uint_as_float(h);
}

__global__ void reset_kernel() {
    if (threadIdx.x < 2*NB) g_flags[threadIdx.x*32] = 0u;
}
__global__ void nop_kernel() {}

// ---- Phase 1: pre = x @ W_in^T (f32x2 packed) ------------------------------
__global__ void __launch_bounds__(256) pre_kernel(const float* __restrict__ x,
                                                  const float* __restrict__ Win)
{
    __shared__ __align__(16) float xs[32*68];
    size_t rowBase = (size_t)blockIdx.x*32;
    for (int idx = threadIdx.x; idx < 32*64; idx += 256)
        xs[(idx>>6)*68 + (idx&63)] = x[(rowBase + (idx>>6))*64 + (idx&63)];
    __syncthreads();
    for (int jj = 0; jj < 4; jj++) {
        int j = jj*256 + threadIdx.x;
        ull w[32];
        const ull* wp = (const ull*)(Win + (size_t)j*64);
#pragma unroll
        for (int q = 0; q < 32; q++) w[q] = wp[q];
#pragma unroll 1
        for (int r = 0; r < 32; r++) {
            const ull* xr = (const ull*)&xs[r*68];
            ull a = 0, b = 0, c = 0, d = 0;
#pragma unroll
            for (int q = 0; q < 32; q += 4) {
                fma2(a, w[q], xr[q]);     fma2(b, w[q+1], xr[q+1]);
                fma2(c, w[q+2], xr[q+2]); fma2(d, w[q+3], xr[q+3]);
            }
            g_pre[(rowBase + r)*Rk + j] = (hsum2(a)+hsum2(b))+(hsum2(c)+hsum2(d));
        }
    }
}

// ---------------------------------------------------------------------------
// Phase 2: two independent engines per block, warp-specialized.
// Engine e (warps e*8..e*8+7): chain of 16 batches [e*16 .. e*16+16).
// Block (pb,pj): engine handles its chain's batches pb*4..pb*4+4, j [pj*32,+32).
// Each engine: k-split 8 warps x 128k; W pairs from SMEM; R7-style flag ring.
// NO block-wide synchronization inside the time loop.
// ---------------------------------------------------------------------------
__global__ void __launch_bounds__(THREADS, 1) esn_main(const float* __restrict__ Wres)
{
    extern __shared__ __align__(16) float sm[];
    char* smc = (char*)sm;
    const int tid = threadIdx.x, wid = tid >> 5, lane = tid & 31;
    const int e   = wid >> 3;                 // engine 0/1
    const int w8  = wid & 7;                  // warp within engine
    const int pb  = blockIdx.x >> 5, pj = blockIdx.x & 31;
    const int j0  = pj*JPB;
    const int kb  = w8*64;                    // kp base (64 kp = 128 k per warp)
    const int gbase = e*16 + pb*4;            // global batch base for epi warps

    char*  WT    = smc + WT_B;
    char*  rPe   = smc + (e ? RPB_B : RPA_B);
    char*  redeB = smc + (e ? REDB_B : REDA_B);
    float* rbufE = e ? g_rbufB : g_rbufA;
    unsigned* flagsE = g_flags + (size_t)e*NB*32;

    // ---- one-time init: W pairs into SMEM, zero rP
    for (int jl = 0; jl < JPB; jl++) {
        float2 v = *(const float2*)(Wres + (size_t)(j0 + jl)*Rk + 2*tid);
        *(float2*)(WT + (size_t)tid*264 + jl*8) = v;
    }
    for (int i = tid; i < (2*24576)/4; i += THREADS)
        *(float*)(smc + RPA_B + i*4) = 0.f;
    __syncthreads();

    const unsigned* fp = flagsE + (size_t)(pb*32 + w8*4 + (lane & 3))*32;
    unsigned* relp = flagsE + (size_t)blockIdx.x*32;

    for (int t = 0; t < Sk; t++) {
        // epi warps: early preval load (latency hides under poll/stage/kloop)
        float preval = 0.f;
        if (w8 < 4)
            preval = g_pre[((size_t)(gbase + w8)*Sk + t)*Rk + j0 + lane];

        if (t > 0) {   // wait for this warp's 4 producer blocks (same chain, pb)
            unsigned v;
            do { asm volatile("ld.acquire.gpu.global.u32 %0, [%1];"
                              : "=r"(v) : "l"(fp) : "memory"); } while (v < (unsigned)t);
        }
        __syncwarp();

        if (t > 0) {   // stage 4 batches x 64 kp (relaxed.gpu: L1-bypass, L2 coherent)
            const float* src = rbufE + (size_t)((t-1)&1)*(16*Rk);
#pragma unroll
            for (int bl = 0; bl < 4; bl++) {
#pragma unroll
                for (int h = 0; h < 2; h++) {
                    int kpx = kb + h*32 + lane;
                    float2 v;
                    asm volatile("ld.relaxed.gpu.global.v2.f32 {%0,%1}, [%2];"
                                 : "=f"(v.x), "=f"(v.y)
                                 : "l"(src + (size_t)(pb*4 + bl)*Rk + 2*kpx) : "memory");
                    *(float2*)(rPe + (size_t)kpx*48 + bl*8) = v;
                }
            }
        }
        __syncwarp();

        // ---- K-loop: 64 kp, W pairs from SMEM (LDS.64), r pairs broadcast
        ull a0=0, a1=0, a2=0, a3=0;
#pragma unroll 8
        for (int u = 0; u < 64; u++) {
            ull w = *(const ull*)(WT + (size_t)(kb + u)*264 + lane*8);
            const ulonglong2* rp = (const ulonglong2*)(rPe + (size_t)(kb + u)*48);
            ulonglong2 q = rp[0];
            fma2(a0, w, q.x); fma2(a1, w, q.y);
            ull q2 = *(const ull*)(rPe + (size_t)(kb + u)*48 + 16);
            ull q3 = *(const ull*)(rPe + (size_t)(kb + u)*48 + 24);
            fma2(a2, w, q2); fma2(a3, w, q3);
        }
        float* red = (float*)(redeB + (t & 1)*4224);
        red[(w8*4+0)*33+lane] = hsum2(a0); red[(w8*4+1)*33+lane] = hsum2(a1);
        red[(w8*4+2)*33+lane] = hsum2(a2); red[(w8*4+3)*33+lane] = hsum2(a3);

        // engine-local barrier (all 8 warps of this engine)
        asm volatile("bar.sync %0, 256;" :: "r"(1 + e) : "memory");

        if (w8 < 4) {   // epilogue: warp w8 = batch, lane = j
            float s = preval;
#pragma unroll
            for (int kc = 0; kc < 8; kc++) s += red[(kc*4 + w8)*33 + lane];
            float ex = __expf(2.f*fabsf(s));
            float rv = copysignf(1.f - __fdividef(2.f, ex + 1.f), s);
            if (t < Sk - 1)
                rbufE[(size_t)(t&1)*(16*Rk) + (size_t)(pb*4 + w8)*Rk + j0 + lane] = rv;
            // epi-warps barrier, then single release
            asm volatile("bar.sync %0, 128;" :: "r"(3 + e) : "memory");
            if (w8 == 0 && lane == 0 && t < Sk - 1)
                asm volatile("st.release.gpu.global.u32 [%0], %1;"
                             :: "l"(relp), "r"((unsigned)(t+1)) : "memory");
            // history store off the release path
            g_rs[((size_t)(gbase + w8)*Sk + t)*Rk + j0 + lane] = rv;
        }
        // warps 4-7 fall straight through to next step's poll
    }
}

// ---- Phase 3: out = [x, rs] @ W_out^T --------------------------------------
__global__ void __launch_bounds__(256) out_kernel(const float* __restrict__ x,
                                                  const float* __restrict__ Wout,
                                                  float* __restrict__ out)
{
    __shared__ float ws[Ok*1088];
    for (int idx = threadIdx.x; idx < Ok*1088; idx += 256) ws[idx] = Wout[idx];
    __syncthreads();
    int warp = threadIdx.x >> 5, lane = threadIdx.x & 31;
    for (size_t row = (size_t)blockIdx.x*8 + warp; row < (size_t)Bk*Sk;
         row += (size_t)gridDim.x*8) {
        const float* xr = x + row*Ik;
        const float* rr = g_rs + row*Rk;
        float acc[8] = {0,0,0,0,0,0,0,0};
#pragma unroll
        for (int q = 0; q < 2; q++) {
            int k = q*32 + lane; float f = xr[k];
#pragma unroll
            for (int o = 0; o < 8; o++) acc[o] = fmaf(f, ws[o*1088 + k], acc[o]);
        }
#pragma unroll 4
        for (int q = 0; q < 32; q++) {
            int k = q*32 + lane; float f = rr[k];
#pragma unroll
            for (int o = 0; o < 8; o++) acc[o] = fmaf(f, ws[o*1088 + 64 + k], acc[o]);
        }
#pragma unroll
        for (int o = 0; o < 8; o++)
#pragma unroll
            for (int off = 16; off; off >>= 1)
                acc[o] += __shfl_xor_sync(0xffffffffu, acc[o], off);
        if (lane == 0)
#pragma unroll
            for (int o = 0; o < 8; o++) out[row*Ok + o] = acc[o];
    }
}

extern "C" void kernel_launch(void* const* d_in, const int* in_sizes, int n_in,
                              void* d_out, int out_size)
{
    (void)in_sizes; (void)n_in; (void)out_size;
    const float* x    = (const float*)d_in[0];
    const float* Win  = (const float*)d_in[1];
    const float* Wres = (const float*)d_in[2];
    const float* Wout = (const float*)d_in[3];
    cudaFuncSetAttribute(esn_main, cudaFuncAttributeMaxDynamicSharedMemorySize,
                         SMEM_BYTES);
    reset_kernel<<<1, 256>>>();
    pre_kernel<<<(Bk*Sk)/32, 256>>>(x, Win);
    nop_kernel<<<1, 32>>>();    // 2 harness pre-launches + reset + pre + nop
    esn_main<<<NB, THREADS, SMEM_BYTES>>>(Wres);   // process-launch idx 5 (ncu -s 5)
    out_kernel<<<2048, 256>>>(x, Wout, (float*)d_out);
}

// round 12
// speedup vs baseline: 1.0909x; 1.0909x over previous
#include <cuda_runtime.h>
#include <cstdint>
typedef unsigned long long ull;

#define Bk 32
#define Sk 4096
#define Ik 64
#define Rk 1024
#define Ok 8

#define NB 128
#define BPB 8        // batches per block
#define JPB 32       // j per block
#define RPB 80       // bytes per k-pair row in rP
#define STP 1026     // W staging pitch (floats)
#define SMEM_BYTES (JPB*STP*4)   // 131328; covers rP(40960)+red(8448)

__device__ float g_pre[(size_t)Bk*Sk*Rk];
__device__ float g_rs [(size_t)Bk*Sk*Rk];
__device__ float g_rbuf[2*Bk*Rk];
__device__ unsigned g_flags[NB*32];

__device__ __forceinline__ void fma2(ull& a, ull b, ull c) {
    asm("fma.rn.f32x2 %0, %1, %2, %0;" : "+l"(a) : "l"(b), "l"(c));
}
__device__ __forceinline__ float hsum2(ull a) {
    unsigned l, h; asm("mov.b64 {%0,%1}, %2;" : "=r"(l), "=r"(h) : "l"(a));
    return __uint_as_float(l) + __uint_as_float(h);
}

__global__ void reset_kernel() {
    if (threadIdx.x < NB) g_flags[threadIdx.x*32] = 0u;
}
__global__ void nop_kernel() {}

// ---- Phase 1: pre = x @ W_in^T (f32x2 packed) ------------------------------
__global__ void __launch_bounds__(256) pre_kernel(const float* __restrict__ x,
                                                  const float* __restrict__ Win)
{
    __shared__ __align__(16) float xs[32*68];
    size_t rowBase = (size_t)blockIdx.x*32;
    for (int idx = threadIdx.x; idx < 32*64; idx += 256)
        xs[(idx>>6)*68 + (idx&63)] = x[(rowBase + (idx>>6))*64 + (idx&63)];
    __syncthreads();
    for (int jj = 0; jj < 4; jj++) {
        int j = jj*256 + threadIdx.x;
        ull w[32];
        const ull* wp = (const ull*)(Win + (size_t)j*64);
#pragma unroll
        for (int q = 0; q < 32; q++) w[q] = wp[q];
#pragma unroll 1
        for (int r = 0; r < 32; r++) {
            const ull* xr = (const ull*)&xs[r*68];
            ull a = 0, b = 0, c = 0, d = 0;
#pragma unroll
            for (int q = 0; q < 32; q += 4) {
                fma2(a, w[q], xr[q]);     fma2(b, w[q+1], xr[q+1]);
                fma2(c, w[q+2], xr[q+2]); fma2(d, w[q+3], xr[q+3]);
            }
            g_pre[(rowBase + r)*Rk + j] = (hsum2(a)+hsum2(b))+(hsum2(c)+hsum2(d));
        }
    }
}

// ---------------------------------------------------------------------------
// Phase 2: persistent recurrence, R7 exchange + CHUNKED pipelined K-loop.
// Warp's 128-k range = 4 producer blocks' outputs; each 16-kp chunk is
// polled, loaded, staged and FMA'd independently, software-pipelined so
// chunk c+1's poll+LDG hides under chunk c's FMA.
// ---------------------------------------------------------------------------
__global__ void __launch_bounds__(256, 1) esn_main(const float* __restrict__ Wres)
{
    extern __shared__ __align__(16) float sm[];
    char* smc = (char*)sm;
    const int tid = threadIdx.x, wid = tid >> 5, lane = tid & 31;
    const int pb = blockIdx.x >> 5, pj = blockIdx.x & 31;
    const int b0 = pb*BPB, j0 = pj*JPB;
    const int kp0 = wid*64;                       // 64 k-pairs per warp
    const int kq  = lane & 15, bh = lane >> 4;    // LDG lane mapping

    // stage W slice, pull this thread's 64 (even,odd) weight pairs into regs
    for (int jl = 0; jl < JPB; jl++) {
        const float* src = Wres + (size_t)(j0 + jl)*Rk;
        for (int k = tid; k < Rk; k += 256) sm[jl*STP + k] = src[k];
    }
    __syncthreads();
    ull w2[64];
    {
        const ull* ws = (const ull*)(sm + lane*STP);
#pragma unroll
        for (int u = 0; u < 64; u++) w2[u] = ws[kp0 + u];
    }
    __syncthreads();

    char*  rP  = smc;                              // [512 kp][RPB], warp-private
    float* red = (float*)(smc + 512*RPB);          // [64][33]
    const unsigned* fbase = g_flags + (size_t)(pb*32 + wid*4)*32;

    for (int t = 0; t < Sk; t++) {
        float preval = g_pre[((size_t)(b0 + wid)*Sk + t)*Rk + (j0 + lane)];

        ull a0=0,a1=0,a2=0,a3=0,a4=0,a5=0,a6=0,a7=0;
        if (t > 0) {
            const float2* src = (const float2*)(g_rbuf + (size_t)((t-1)&1)*(Bk*Rk));
            float2 cur[4], nxt[4];
            // prologue: chunk 0 poll + load
            {
                unsigned v;
                do { asm volatile("ld.acquire.gpu.global.u32 %0, [%1];"
                                  : "=r"(v) : "l"(fbase) : "memory"); } while (v < (unsigned)t);
                int kpx = kp0 + kq;
#pragma unroll
                for (int q = 0; q < 4; q++)
                    cur[q] = src[(size_t)(b0 + bh*4 + q)*(Rk/2) + kpx];
            }
#pragma unroll
            for (int c = 0; c < 4; c++) {
                if (c < 3) {        // poll + load chunk c+1 (flies under FMA of c)
                    const unsigned* fp = fbase + (size_t)(c + 1)*32;
                    unsigned v;
                    do { asm volatile("ld.acquire.gpu.global.u32 %0, [%1];"
                                      : "=r"(v) : "l"(fp) : "memory"); } while (v < (unsigned)t);
                    int kpx = kp0 + (c + 1)*16 + kq;
#pragma unroll
                    for (int q = 0; q < 4; q++)
                        nxt[q] = src[(size_t)(b0 + bh*4 + q)*(Rk/2) + kpx];
                }
                // stage chunk c (waits only on chunk c's LDGs)
                {
                    int kpb = kp0 + c*16 + kq;
#pragma unroll
                    for (int q = 0; q < 4; q++)
                        *(float2*)(rP + (size_t)kpb*RPB + (bh*4 + q)*8) = cur[q];
                }
                __syncwarp();
                // FMA chunk c
                const char* rb = rP + (size_t)(kp0 + c*16)*RPB;
#pragma unroll
                for (int u = 0; u < 16; u++) {
                    const ulonglong2* rp = (const ulonglong2*)(rb + u*RPB);
                    ulonglong2 q0 = rp[0], q1 = rp[1], q2 = rp[2], q3 = rp[3];
                    ull w = w2[c*16 + u];
                    fma2(a0, w, q0.x); fma2(a1, w, q0.y);
                    fma2(a2, w, q1.x); fma2(a3, w, q1.y);
                    fma2(a4, w, q2.x); fma2(a5, w, q2.y);
                    fma2(a6, w, q3.x); fma2(a7, w, q3.y);
                }
                if (c < 3) {
#pragma unroll
                    for (int q = 0; q < 4; q++) cur[q] = nxt[q];
                }
            }
        }
        // (t == 0: partials stay zero — r_{-1} = 0)

        red[(wid*8+0)*33+lane] = hsum2(a0); red[(wid*8+1)*33+lane] = hsum2(a1);
        red[(wid*8+2)*33+lane] = hsum2(a2); red[(wid*8+3)*33+lane] = hsum2(a3);
        red[(wid*8+4)*33+lane] = hsum2(a4); red[(wid*8+5)*33+lane] = hsum2(a5);
        red[(wid*8+6)*33+lane] = hsum2(a6); red[(wid*8+7)*33+lane] = hsum2(a7);
        __syncthreads();

        float rv;
        {   // epilogue: thread (wid=batch-lane, lane=j)
            float s = preval;
#pragma unroll
            for (int kc = 0; kc < 8; kc++) s += red[(kc*8 + wid)*33 + lane];
            float e = __expf(2.f*fabsf(s));
            rv = copysignf(1.f - __fdividef(2.f, e + 1.f), s);
            if (t < Sk - 1)
                g_rbuf[(size_t)(t&1)*(Bk*Rk) + (size_t)(b0 + wid)*Rk + (j0 + lane)] = rv;
        }
        __syncthreads();

        if (tid == 0 && t < Sk - 1) {
            unsigned nv = (unsigned)(t + 1);
            asm volatile("st.release.gpu.global.u32 [%0], %1;"
                         :: "l"(g_flags + (size_t)blockIdx.x*32), "r"(nv) : "memory");
        }
        // DRAM-destined history store, off the release path
        g_rs[((size_t)(b0 + wid)*Sk + t)*Rk + (j0 + lane)] = rv;
    }
}

// ---- Phase 3: out = [x, rs] @ W_out^T --------------------------------------
__global__ void __launch_bounds__(256) out_kernel(const float* __restrict__ x,
                                                  const float* __restrict__ Wout,
                                                  float* __restrict__ out)
{
    __shared__ float ws[Ok*1088];
    for (int idx = threadIdx.x; idx < Ok*1088; idx += 256) ws[idx] = Wout[idx];
    __syncthreads();
    int warp = threadIdx.x >> 5, lane = threadIdx.x & 31;
    for (size_t row = (size_t)blockIdx.x*8 + warp; row < (size_t)Bk*Sk;
         row += (size_t)gridDim.x*8) {
        const float* xr = x + row*Ik;
        const float* rr = g_rs + row*Rk;
        float acc[8] = {0,0,0,0,0,0,0,0};
#pragma unroll
        for (int q = 0; q < 2; q++) {
            int k = q*32 + lane; float f = xr[k];
#pragma unroll
            for (int o = 0; o < 8; o++) acc[o] = fmaf(f, ws[o*1088 + k], acc[o]);
        }
#pragma unroll 4
        for (int q = 0; q < 32; q++) {
            int k = q*32 + lane; float f = rr[k];
#pragma unroll
            for (int o = 0; o < 8; o++) acc[o] = fmaf(f, ws[o*1088 + 64 + k], acc[o]);
        }
#pragma unroll
        for (int o = 0; o < 8; o++)
#pragma unroll
            for (int off = 16; off; off >>= 1)
                acc[o] += __shfl_xor_sync(0xffffffffu, acc[o], off);
        if (lane == 0)
#pragma unroll
            for (int o = 0; o < 8; o++) out[row*Ok + o] = acc[o];
    }
}

extern "C" void kernel_launch(void* const* d_in, const int* in_sizes, int n_in,
                              void* d_out, int out_size)
{
    (void)in_sizes; (void)n_in; (void)out_size;
    const float* x    = (const float*)d_in[0];
    const float* Win  = (const float*)d_in[1];
    const float* Wres = (const float*)d_in[2];
    const float* Wout = (const float*)d_in[3];
    cudaFuncSetAttribute(esn_main, cudaFuncAttributeMaxDynamicSharedMemorySize,
                         SMEM_BYTES);
    reset_kernel<<<1, 128>>>();
    pre_kernel<<<(Bk*Sk)/32, 256>>>(x, Win);
    nop_kernel<<<1, 32>>>();    // 2 harness pre-launches + reset + pre + nop
    esn_main<<<NB, 256, SMEM_BYTES>>>(Wres);   // process-launch idx 5 (ncu -s 5)
    out_kernel<<<2048, 256>>>(x, Wout, (float*)d_out);
}

// round 13
// speedup vs baseline: 1.2241x; 1.1221x over previous
#include <cuda_runtime.h>
#include <cstdint>
typedef unsigned long long ull;

#define Bk 32
#define Sk 4096
#define Ik 64
#define Rk 1024
#define Ok 8

#define NB 128
#define BPB 8        // batches per block
#define JPB 32       // j per block
#define RPB 80       // bytes per k-pair row in rP
#define STP 1026     // W staging pitch (floats)
#define SMEM_BYTES (JPB*STP*4)   // 131328; covers rP(40960)+red(2*8448)

__device__ float g_pre[(size_t)Bk*Sk*Rk];
__device__ float g_rs [(size_t)Bk*Sk*Rk];
__device__ float g_rbuf[2*Bk*Rk];
__device__ unsigned g_flags[NB*32];

__device__ __forceinline__ void fma2(ull& a, ull b, ull c) {
    asm("fma.rn.f32x2 %0, %1, %2, %0;" : "+l"(a) : "l"(b), "l"(c));
}
__device__ __forceinline__ float hsum2(ull a) {
    unsigned l, h; asm("mov.b64 {%0,%1}, %2;" : "=r"(l), "=r"(h) : "l"(a));
    return __uint_as_float(l) + __uint_as_float(h);
}

__global__ void reset_kernel() {
    if (threadIdx.x < NB) g_flags[threadIdx.x*32] = 0u;
}
__global__ void nop_kernel() {}

// ---- Phase 1: pre = x @ W_in^T (f32x2 packed) ------------------------------
__global__ void __launch_bounds__(256) pre_kernel(const float* __restrict__ x,
                                                  const float* __restrict__ Win)
{
    __shared__ __align__(16) float xs[32*68];
    size_t rowBase = (size_t)blockIdx.x*32;
    for (int idx = threadIdx.x; idx < 32*64; idx += 256)
        xs[(idx>>6)*68 + (idx&63)] = x[(rowBase + (idx>>6))*64 + (idx&63)];
    __syncthreads();
    for (int jj = 0; jj < 4; jj++) {
        int j = jj*256 + threadIdx.x;
        ull w[32];
        const ull* wp = (const ull*)(Win + (size_t)j*64);
#pragma unroll
        for (int q = 0; q < 32; q++) w[q] = wp[q];
#pragma unroll 1
        for (int r = 0; r < 32; r++) {
            const ull* xr = (const ull*)&xs[r*68];
            ull a = 0, b = 0, c = 0, d = 0;
#pragma unroll
            for (int q = 0; q < 32; q += 4) {
                fma2(a, w[q], xr[q]);     fma2(b, w[q+1], xr[q+1]);
                fma2(c, w[q+2], xr[q+2]); fma2(d, w[q+3], xr[q+3]);
            }
            g_pre[(rowBase + r)*Rk + j] = (hsum2(a)+hsum2(b))+(hsum2(c)+hsum2(d));
        }
    }
}

// ---------------------------------------------------------------------------
// Phase 2: R7 skeleton + (a) per-lane RED release (no 2nd syncthreads),
// (b) single poll + chunk-pipelined LDG/stage/FMA, (c) red double-buffered.
// ---------------------------------------------------------------------------
__global__ void __launch_bounds__(256, 1) esn_main(const float* __restrict__ Wres)
{
    extern __shared__ __align__(16) float sm[];
    char* smc = (char*)sm;
    const int tid = threadIdx.x, wid = tid >> 5, lane = tid & 31;
    const int pb = blockIdx.x >> 5, pj = blockIdx.x & 31;
    const int b0 = pb*BPB, j0 = pj*JPB;
    const int kp0 = wid*64;                       // 64 k-pairs per warp
    const int fq = lane & 7, bq = lane >> 3;      // staging lane mapping

    // stage W slice, pull this thread's 64 (even,odd) weight pairs into regs
    for (int jl = 0; jl < JPB; jl++) {
        const float* src = Wres + (size_t)(j0 + jl)*Rk;
        for (int k = tid; k < Rk; k += 256) sm[jl*STP + k] = src[k];
    }
    __syncthreads();
    ull w2[64];
    {
        const ull* ws = (const ull*)(sm + lane*STP);
#pragma unroll
        for (int u = 0; u < 64; u++) w2[u] = ws[kp0 + u];
    }
    __syncthreads();

    char* rP   = smc;                              // [512 kp][RPB], warp-private
    char* redb = smc + 512*RPB;                    // 2 x [64][33] floats
    const unsigned* fp = g_flags + (size_t)(pb*32 + wid*4 + (lane & 3))*32;
    unsigned* relp = g_flags + (size_t)blockIdx.x*32;

    for (int t = 0; t < Sk; t++) {
        float preval = g_pre[((size_t)(b0 + wid)*Sk + t)*Rk + (j0 + lane)];

        ull a0=0,a1=0,a2=0,a3=0,a4=0,a5=0,a6=0,a7=0;
        if (t > 0) {
            // single poll: 4 producer flags via lane&3, need >= 256*t
            {
                unsigned tgt = (unsigned)t << 8, v;
                do { asm volatile("ld.acquire.gpu.global.u32 %0, [%1];"
                                  : "=r"(v) : "l"(fp) : "memory"); } while (v < tgt);
            }
            __syncwarp();

            const float4* src4 = (const float4*)(g_rbuf + (size_t)((t-1)&1)*(Bk*Rk));
            const size_t rowA = (size_t)(b0 + 2*bq)*(Rk/4);
            const size_t rowB = (size_t)(b0 + 2*bq + 1)*(Rk/4);
            float4 ca, cb, na, nb;
            // prologue: chunk 0 loads
            ca = src4[rowA + kp0/2 + fq];
            cb = src4[rowB + kp0/2 + fq];
#pragma unroll
            for (int c = 0; c < 4; c++) {
                if (c < 3) {        // issue chunk c+1 LDGs (fly under FMA of c)
                    na = src4[rowA + kp0/2 + (c+1)*8 + fq];
                    nb = src4[rowB + kp0/2 + (c+1)*8 + fq];
                }
                // stage chunk c
                {
                    int r0 = kp0 + c*16 + 2*fq;
                    *(float2*)(rP + (size_t)r0*RPB     + (2*bq)*8)   = make_float2(ca.x, ca.y);
                    *(float2*)(rP + (size_t)(r0+1)*RPB + (2*bq)*8)   = make_float2(ca.z, ca.w);
                    *(float2*)(rP + (size_t)r0*RPB     + (2*bq+1)*8) = make_float2(cb.x, cb.y);
                    *(float2*)(rP + (size_t)(r0+1)*RPB + (2*bq+1)*8) = make_float2(cb.z, cb.w);
                }
                __syncwarp();
                // FMA chunk c
                const char* rb = rP + (size_t)(kp0 + c*16)*RPB;
#pragma unroll
                for (int u = 0; u < 16; u++) {
                    const ulonglong2* rp = (const ulonglong2*)(rb + u*RPB);
                    ulonglong2 q0 = rp[0], q1 = rp[1], q2 = rp[2], q3 = rp[3];
                    ull w = w2[c*16 + u];
                    fma2(a0, w, q0.x); fma2(a1, w, q0.y);
                    fma2(a2, w, q1.x); fma2(a3, w, q1.y);
                    fma2(a4, w, q2.x); fma2(a5, w, q2.y);
                    fma2(a6, w, q3.x); fma2(a7, w, q3.y);
                }
                if (c < 3) { ca = na; cb = nb; }
            }
        }
        // (t == 0: partials stay zero — r_{-1} = 0)

        float* red = (float*)(redb + (t & 1)*8448);
        red[(wid*8+0)*33+lane] = hsum2(a0); red[(wid*8+1)*33+lane] = hsum2(a1);
        red[(wid*8+2)*33+lane] = hsum2(a2); red[(wid*8+3)*33+lane] = hsum2(a3);
        red[(wid*8+4)*33+lane] = hsum2(a4); red[(wid*8+5)*33+lane] = hsum2(a5);
        red[(wid*8+6)*33+lane] = hsum2(a6); red[(wid*8+7)*33+lane] = hsum2(a7);
        __syncthreads();             // sync1: the only block-wide sync per step

        float rv;
        {   // epilogue: thread (wid=batch-lane, lane=j)
            float s = preval;
#pragma unroll
            for (int kc = 0; kc < 8; kc++) s += red[(kc*8 + wid)*33 + lane];
            float e = __expf(2.f*fabsf(s));
            rv = copysignf(1.f - __fdividef(2.f, e + 1.f), s);
            if (t < Sk - 1) {
                g_rbuf[(size_t)(t&1)*(Bk*Rk) + (size_t)(b0 + wid)*Rk + (j0 + lane)] = rv;
                // per-lane release: orders this lane's rbuf store; 256/step total
                asm volatile("red.release.gpu.global.add.u32 [%0], %1;"
                             :: "l"(relp), "r"(1u) : "memory");
            }
        }
        // DRAM-destined history store, off the release path
        g_rs[((size_t)(b0 + wid)*Sk + t)*Rk + (j0 + lane)] = rv;
    }
}

// ---- Phase 3: out = [x, rs] @ W_out^T --------------------------------------
__global__ void __launch_bounds__(256) out_kernel(const float* __restrict__ x,
                                                  const float* __restrict__ Wout,
                                                  float* __restrict__ out)
{
    __shared__ float ws[Ok*1088];
    for (int idx = threadIdx.x; idx < Ok*1088; idx += 256) ws[idx] = Wout[idx];
    __syncthreads();
    int warp = threadIdx.x >> 5, lane = threadIdx.x & 31;
    for (size_t row = (size_t)blockIdx.x*8 + warp; row < (size_t)Bk*Sk;
         row += (size_t)gridDim.x*8) {
        const float* xr = x + row*Ik;
        const float* rr = g_rs + row*Rk;
        float acc[8] = {0,0,0,0,0,0,0,0};
#pragma unroll
        for (int q = 0; q < 2; q++) {
            int k = q*32 + lane; float f = xr[k];
#pragma unroll
            for (int o = 0; o < 8; o++) acc[o] = fmaf(f, ws[o*1088 + k], acc[o]);
        }
#pragma unroll 4
        for (int q = 0; q < 32; q++) {
            int k = q*32 + lane; float f = rr[k];
#pragma unroll
            for (int o = 0; o < 8; o++) acc[o] = fmaf(f, ws[o*1088 + 64 + k], acc[o]);
        }
#pragma unroll
        for (int o = 0; o < 8; o++)
#pragma unroll
            for (int off = 16; off; off >>= 1)
                acc[o] += __shfl_xor_sync(0xffffffffu, acc[o], off);
        if (lane == 0)
#pragma unroll
            for (int o = 0; o < 8; o++) out[row*Ok + o] = acc[o];
    }
}

extern "C" void kernel_launch(void* const* d_in, const int* in_sizes, int n_in,
                              void* d_out, int out_size)
{
    (void)in_sizes; (void)n_in; (void)out_size;
    const float* x    = (const float*)d_in[0];
    const float* Win  = (const float*)d_in[1];
    const float* Wres = (const float*)d_in[2];
    const float* Wout = (const float*)d_in[3];
    cudaFuncSetAttribute(esn_main, cudaFuncAttributeMaxDynamicSharedMemorySize,
                         SMEM_BYTES);
    reset_kernel<<<1, 128>>>();
    pre_kernel<<<(Bk*Sk)/32, 256>>>(x, Win);
    nop_kernel<<<1, 32>>>();    // 2 harness pre-launches + reset + pre + nop
    esn_main<<<NB, 256, SMEM_BYTES>>>(Wres);   // process-launch idx 5 (ncu -s 5)
    out_kernel<<<2048, 256>>>(x, Wout, (float*)d_out);
}